// round 6
// baseline (speedup 1.0000x reference)
#include <cuda_runtime.h>
#include <cuda_fp16.h>
#include <math.h>
#include <stdint.h>

// Problem constants
#define Bb 2
#define Nn 2048
#define Hh 1024
#define NH 16
#define HD 64
#define SCALE 0.125f
#define Kdim 1024
#define M_TOT (Bb*Nn)   // 4096

// ---------------------------------------------------------------------------
// Scratch (device globals; no allocations allowed)
// ---------------------------------------------------------------------------
__device__ __align__(128) __half g_Xhi [M_TOT*Kdim];   // x split (exact)
__device__ __align__(128) __half g_Xlo [M_TOT*Kdim];
__device__ __align__(128) __half g_X2hi[M_TOT*Kdim];
__device__ __align__(128) __half g_X2lo[M_TOT*Kdim];
__device__ __align__(128) __half g_Wq  [3*Hh*Kdim];    // Wqkv^T [3072][1024] single fp16
__device__ __align__(128) __half g_Wo  [Hh*Kdim];      // Wout^T single fp16
// head-major [b,h,n,d]
__device__ __align__(128) __half g_Qh  [Bb*NH*Nn*HD];  // Q single fp16
__device__ __align__(128) __half g_Khi [Bb*NH*Nn*HD];  // K split
__device__ __align__(128) __half g_Klo [Bb*NH*Nn*HD];
__device__ __align__(128) __half g_Vhi [Bb*NH*Nn*HD];  // V split
__device__ __align__(128) __half g_Vlo [Bb*NH*Nn*HD];
__device__ __align__(128) __half g_Ahi [M_TOT*Hh];     // attn out split [b*n][h*d]
__device__ __align__(128) __half g_Alo [M_TOT*Hh];

// ---------------------------------------------------------------------------
// PTX helpers
// ---------------------------------------------------------------------------
__device__ __forceinline__ uint32_t smem_u32(const void* p) {
    return (uint32_t)__cvta_generic_to_shared(p);
}
__device__ __forceinline__ void cp_async16(uint32_t d, const void* s) {
    asm volatile("cp.async.cg.shared.global [%0], [%1], 16;\n" :: "r"(d), "l"(s) : "memory");
}
__device__ __forceinline__ void cp_commit() { asm volatile("cp.async.commit_group;\n" ::: "memory"); }
__device__ __forceinline__ void cp_wait1()  { asm volatile("cp.async.wait_group 1;\n" ::: "memory"); }
__device__ __forceinline__ void cp_wait2()  { asm volatile("cp.async.wait_group 2;\n" ::: "memory"); }
__device__ __forceinline__ void ldsm_x4(uint32_t& r0, uint32_t& r1, uint32_t& r2, uint32_t& r3, uint32_t a) {
    asm volatile("ldmatrix.sync.aligned.m8n8.x4.shared.b16 {%0,%1,%2,%3}, [%4];"
                 : "=r"(r0), "=r"(r1), "=r"(r2), "=r"(r3) : "r"(a));
}
__device__ __forceinline__ void ldsm_x4_t(uint32_t& r0, uint32_t& r1, uint32_t& r2, uint32_t& r3, uint32_t a) {
    asm volatile("ldmatrix.sync.aligned.m8n8.x4.trans.shared.b16 {%0,%1,%2,%3}, [%4];"
                 : "=r"(r0), "=r"(r1), "=r"(r2), "=r"(r3) : "r"(a));
}
__device__ __forceinline__ void mma16816(float c[4], const uint32_t a[4], const uint32_t b[2]) {
    asm volatile("mma.sync.aligned.m16n8k16.row.col.f32.f16.f16.f32 "
                 "{%0,%1,%2,%3}, {%4,%5,%6,%7}, {%8,%9}, {%0,%1,%2,%3};"
                 : "+f"(c[0]), "+f"(c[1]), "+f"(c[2]), "+f"(c[3])
                 : "r"(a[0]), "r"(a[1]), "r"(a[2]), "r"(a[3]), "r"(b[0]), "r"(b[1]));
}
__device__ __forceinline__ float ex2f(float x) {
    float y; asm("ex2.approx.f32 %0, %1;" : "=f"(y) : "f"(x)); return y;
}
__device__ __forceinline__ uint32_t packh(float a, float b) {
    __half2 v = __halves2half2(__float2half_rn(a), __float2half_rn(b));
    return *(uint32_t*)&v;
}

// ---------------------------------------------------------------------------
// GEMM tiling: A split hi/lo + B single = 3 tiles per chunk
// ---------------------------------------------------------------------------
#define BMt 128
#define BNt 128
#define KCc 32
#define PITCHB 80                   // 32 fp16 (64B) + 16 pad
#define TILE_BYTES (128*PITCHB)     // 10240
#define BUF_BYTES (3*TILE_BYTES)    // Ahi|Alo|B = 30720
#define GEMM_SMEM (3*BUF_BYTES)     // 3 stages = 92160

// ---------------------------------------------------------------------------
// fp32 -> fp16 hi/lo split (element-wise)
// ---------------------------------------------------------------------------
__global__ __launch_bounds__(256) void split_kernel(const float* __restrict__ src,
                                                    __half* __restrict__ hi,
                                                    __half* __restrict__ lo,
                                                    int n4)
{
    int i = blockIdx.x * blockDim.x + threadIdx.x;
    if (i >= n4) return;
    float4 v = ((const float4*)src)[i];
    __half h0 = __float2half_rn(v.x), h1 = __float2half_rn(v.y),
           h2 = __float2half_rn(v.z), h3 = __float2half_rn(v.w);
    __half l0 = __float2half_rn(v.x - __half2float(h0));
    __half l1 = __float2half_rn(v.y - __half2float(h1));
    __half l2 = __float2half_rn(v.z - __half2float(h2));
    __half l3 = __float2half_rn(v.w - __half2float(h3));
    __half2* H = (__half2*)(hi + (size_t)i * 4);
    H[0] = __halves2half2(h0, h1); H[1] = __halves2half2(h2, h3);
    __half2* L = (__half2*)(lo + (size_t)i * 4);
    L[0] = __halves2half2(l0, l1); L[1] = __halves2half2(l2, l3);
}

// Transpose + convert: src [1024][C] fp32 -> dst [C][1024] fp16 single
__global__ __launch_bounds__(256) void tconv_kernel(const float* __restrict__ src,
                                                    __half* __restrict__ dst,
                                                    int C)
{
    __shared__ float tile[32][33];
    int c0 = blockIdx.x * 32, k0 = blockIdx.y * 32;
    int tx = threadIdx.x, ty = threadIdx.y;  // 32x8
#pragma unroll
    for (int i = 0; i < 32; i += 8)
        tile[ty + i][tx] = src[(size_t)(k0 + ty + i) * C + c0 + tx];
    __syncthreads();
#pragma unroll
    for (int i = 0; i < 32; i += 8)
        dst[(size_t)(c0 + ty + i) * 1024 + k0 + tx] = __float2half_rn(tile[tx][ty + i]);
}

// ---------------------------------------------------------------------------
// HMMA GEMM mainloop: C[128,128] = (Ahi+Alo)@B^T, K=1024, 2 mma passes/chunk
// 3-stage cp.async pipeline, one __syncthreads per chunk.
// ---------------------------------------------------------------------------
__device__ __forceinline__ void load_chunk(const __half* A0, const __half* A1,
                                           const __half* B0,
                                           uint32_t smbuf, int c, int tid)
{
    int row  = tid >> 1;
    int half = (tid & 1) * 2;
    size_t g = (size_t)row * Kdim + (size_t)c * KCc + half * 8;
    uint32_t s = smbuf + row * PITCHB + half * 16;
    cp_async16(s,                       A0 + g);
    cp_async16(s + 16,                  A0 + g + 8);
    cp_async16(s + TILE_BYTES,          A1 + g);
    cp_async16(s + TILE_BYTES + 16,     A1 + g + 8);
    cp_async16(s + 2 * TILE_BYTES,      B0 + g);
    cp_async16(s + 2 * TILE_BYTES + 16, B0 + g + 8);
}

__device__ __forceinline__ void ldA(uint32_t smA, int wm, int lane, int k0, uint32_t a[4][4]) {
    int lrow = lane & 15;
    int lcol = (lane >> 4) * 8 + k0;
#pragma unroll
    for (int mt = 0; mt < 4; mt++)
        ldsm_x4(a[mt][0], a[mt][1], a[mt][2], a[mt][3],
                smA + (wm + mt * 16 + lrow) * PITCHB + lcol * 2);
}
__device__ __forceinline__ void ldB(uint32_t smB, int wn, int lane, int k0, uint32_t b[4][2]) {
    int brow = ((lane >> 4) & 1) * 8 + (lane & 7);
    int bcol = ((lane >> 3) & 1) * 8 + k0;
#pragma unroll
    for (int j2 = 0; j2 < 2; j2++) {
        uint32_t r0, r1, r2, r3;
        ldsm_x4(r0, r1, r2, r3, smB + (wn + j2 * 16 + brow) * PITCHB + bcol * 2);
        b[j2 * 2][0] = r0; b[j2 * 2][1] = r1;
        b[j2 * 2 + 1][0] = r2; b[j2 * 2 + 1][1] = r3;
    }
}

__device__ __forceinline__ void gemm_mainloop(const __half* Ahi, const __half* Alo,
                                              const __half* B,
                                              uint32_t smb, int tid, float acc[4][4][4])
{
    const int wid = tid >> 5, lane = tid & 31;
    const int wm = (wid >> 2) * 64, wn = (wid & 3) * 32;
    const int NCH = Kdim / KCc;  // 32

    load_chunk(Ahi, Alo, B, smb,             0, tid); cp_commit();
    load_chunk(Ahi, Alo, B, smb + BUF_BYTES, 1, tid); cp_commit();

    int stage = 0, wstage = 2;
    for (int c = 0; c < NCH; ++c) {
        uint32_t buf = smb + stage * BUF_BYTES;
        cp_wait1();
        __syncthreads();

        uint32_t smA_hi = buf, smA_lo = buf + TILE_BYTES, smB = buf + 2 * TILE_BYTES;
#pragma unroll
        for (int ks = 0; ks < 2; ks++) {
            int k0 = ks * 16;
            uint32_t ah[4][4], al[4][4], bb[4][2];
            ldA(smA_hi, wm, lane, k0, ah);
            ldB(smB, wn, lane, k0, bb);
#pragma unroll
            for (int mt = 0; mt < 4; mt++)
#pragma unroll
                for (int nt = 0; nt < 4; nt++) mma16816(acc[mt][nt], ah[mt], bb[nt]);
            ldA(smA_lo, wm, lane, k0, al);
#pragma unroll
            for (int mt = 0; mt < 4; mt++)
#pragma unroll
                for (int nt = 0; nt < 4; nt++) mma16816(acc[mt][nt], al[mt], bb[nt]);
        }
        if (c + 2 < NCH)
            load_chunk(Ahi, Alo, B, smb + wstage * BUF_BYTES, c + 2, tid);
        cp_commit();
        stage = (stage + 1) % 3; wstage = (wstage + 1) % 3;
    }
}

// ---------------------------------------------------------------------------
// QKV GEMM: z=0: Q=x@Wq (single fp16 out); z=1: K=x2@Wk (split); z=2: V (split)
// ---------------------------------------------------------------------------
__global__ __launch_bounds__(256) void qkv_mma_kernel()
{
    extern __shared__ char sm[];
    uint32_t smb = smem_u32(sm);
    int tid = threadIdx.x;
    int z = blockIdx.z;
    int n0 = blockIdx.x * BNt;
    int m0 = blockIdx.y * BMt;

    const __half* Ahi = (z == 0 ? g_Xhi : g_X2hi) + (size_t)m0 * Kdim;
    const __half* Alo = (z == 0 ? g_Xlo : g_X2lo) + (size_t)m0 * Kdim;
    const __half* B   = g_Wq + (size_t)(z * Hh + n0) * Kdim;

    float acc[4][4][4];
#pragma unroll
    for (int i = 0; i < 4; i++)
#pragma unroll
        for (int j = 0; j < 4; j++)
#pragma unroll
            for (int k = 0; k < 4; k++) acc[i][j][k] = 0.f;

    gemm_mainloop(Ahi, Alo, B, smb, tid, acc);

    const int wid = tid >> 5, lane = tid & 31;
    const int wm = (wid >> 2) * 64, wn = (wid & 3) * 32;
#pragma unroll
    for (int mt = 0; mt < 4; mt++) {
#pragma unroll
        for (int nt = 0; nt < 4; nt++) {
            int col = n0 + wn + nt * 8 + (lane & 3) * 2;
            int h = col >> 6, d = col & 63;
#pragma unroll
            for (int half = 0; half < 2; half++) {
                int gm = m0 + wm + mt * 16 + (lane >> 2) + half * 8;
                int b = gm / Nn, n = gm % Nn;
                float v0 = acc[mt][nt][half * 2], v1 = acc[mt][nt][half * 2 + 1];
                size_t idx = ((((size_t)b * NH + h) * Nn) + n) * HD + d;
                if (z == 0) {
                    *(uint32_t*)(g_Qh + idx) = packh(v0, v1);
                } else {
                    float h0 = __half2float(__float2half_rn(v0));
                    float h1 = __half2float(__float2half_rn(v1));
                    __half* dhi = (z == 1) ? g_Khi : g_Vhi;
                    __half* dlo = (z == 1) ? g_Klo : g_Vlo;
                    *(uint32_t*)(dhi + idx) = packh(h0, h1);
                    *(uint32_t*)(dlo + idx) = packh(v0 - h0, v1 - h1);
                }
            }
        }
    }
}

// ---------------------------------------------------------------------------
// Output projection GEMM: out = attn @ Wout + bout
// ---------------------------------------------------------------------------
__global__ __launch_bounds__(256) void proj_mma_kernel(const float* __restrict__ bout,
                                                       float* __restrict__ out)
{
    extern __shared__ char sm[];
    uint32_t smb = smem_u32(sm);
    int tid = threadIdx.x;
    int n0 = blockIdx.x * BNt;
    int m0 = blockIdx.y * BMt;

    const __half* Ahi = g_Ahi + (size_t)m0 * Kdim;
    const __half* Alo = g_Alo + (size_t)m0 * Kdim;
    const __half* B   = g_Wo + (size_t)n0 * Kdim;

    float acc[4][4][4];
#pragma unroll
    for (int i = 0; i < 4; i++)
#pragma unroll
        for (int j = 0; j < 4; j++)
#pragma unroll
            for (int k = 0; k < 4; k++) acc[i][j][k] = 0.f;

    gemm_mainloop(Ahi, Alo, B, smb, tid, acc);

    const int wid = tid >> 5, lane = tid & 31;
    const int wm = (wid >> 2) * 64, wn = (wid & 3) * 32;
#pragma unroll
    for (int mt = 0; mt < 4; mt++) {
#pragma unroll
        for (int nt = 0; nt < 4; nt++) {
            int col = n0 + wn + nt * 8 + (lane & 3) * 2;
            float2 bb = *(const float2*)(bout + col);
#pragma unroll
            for (int half = 0; half < 2; half++) {
                int gm = m0 + wm + mt * 16 + (lane >> 2) + half * 8;
                float2 o = make_float2(acc[mt][nt][half * 2] + bb.x,
                                       acc[mt][nt][half * 2 + 1] + bb.y);
                *(float2*)(out + (size_t)gm * 1024 + col) = o;
            }
        }
    }
}

// ---------------------------------------------------------------------------
// Tensor-core flash attention — fp16, 2-pass S (Kh/Kl) + 2-pass PV (Vh/Vl)
// ---------------------------------------------------------------------------
#define APITCHB 144
#define QT 128
#define KVT 64
#define MATB (64*APITCHB)              // 9216 bytes per kv matrix
#define KVBUF (4*MATB)                 // Khi|Klo|Vhi|Vlo = 36864
#define QBYTES (128*APITCHB)           // 18432 (Q single)
#define ATTN_SMEM (QBYTES + 3*KVBUF)   // 129024

__device__ __forceinline__ void load_kv_tile(const __half* const mats[4],
                                             uint32_t bufb, int t, int tid)
{
#pragma unroll
    for (int i = 0; i < 8; i++) {
        int e = tid + i * 256;
        int mat = e >> 9;
        int row = (e >> 3) & 63;
        int c   = e & 7;
        cp_async16(bufb + mat * MATB + row * APITCHB + c * 16,
                   mats[mat] + ((size_t)(t * KVT + row)) * HD + c * 8);
    }
}

__global__ __launch_bounds__(256, 1) void attn_mma_kernel()
{
    extern __shared__ char sm[];
    uint32_t smb = smem_u32(sm);
    const uint32_t QS  = smb;
    const uint32_t KV0 = smb + QBYTES;

    const int tid = threadIdx.x, lane = tid & 31, wid = tid >> 5;
    const int bh = blockIdx.y, q0 = blockIdx.x * QT;

    const size_t base = (size_t)bh * Nn * HD;
    const __half* Qp = g_Qh + base + (size_t)q0 * HD;
    const __half* kvmats[4] = { g_Khi + base, g_Klo + base, g_Vhi + base, g_Vlo + base };

    // Load Q (single): 128 rows x 8 16B-chunks = 1024 -> 4/thread
#pragma unroll
    for (int i = 0; i < 4; i++) {
        int e = tid + i * 256;
        int row = e >> 3;
        int c   = e & 7;
        cp_async16(QS + row * APITCHB + c * 16, Qp + (size_t)row * HD + c * 8);
    }
    cp_commit();
    load_kv_tile(kvmats, KV0, 0, tid);          cp_commit();
    load_kv_tile(kvmats, KV0 + KVBUF, 1, tid);  cp_commit();

    cp_wait2();         // Q ready
    __syncthreads();

    // Q fragments (once)
    uint32_t aq[4][4];
    {
        int lrow = lane & 15;
        int lcolB = (lane >> 4) * 16;
        uint32_t qrow = (wid * 16 + lrow) * APITCHB + lcolB;
#pragma unroll
        for (int kt = 0; kt < 4; kt++)
            ldsm_x4(aq[kt][0], aq[kt][1], aq[kt][2], aq[kt][3], QS + qrow + kt * 32);
    }

    float O[8][4];
#pragma unroll
    for (int i = 0; i < 8; i++)
#pragma unroll
        for (int j = 0; j < 4; j++) O[i][j] = 0.f;
    float m0 = -INFINITY, m1 = -INFINITY, l0 = 0.f, l1 = 0.f;
    const float cc = SCALE * 1.4426950408889634f;   // scale * log2(e)

    const int brow = ((lane >> 4) & 1) * 8 + (lane & 7);      // K (non-trans)
    const int bcolB = ((lane >> 3) & 1) * 16;
    const int vrow = lane & 15;                                // V (trans)
    const int vcolB = ((lane >> 4) & 1) * 16;

    int stage = 0, wstage = 2;
    for (int t = 0; t < Nn / KVT; ++t) {
        uint32_t buf = KV0 + stage * KVBUF;
        cp_wait1();
        __syncthreads();

        uint32_t KHIb = buf, KLOb = buf + MATB, VHIb = buf + 2 * MATB, VLOb = buf + 3 * MATB;

        // ---- S = Q K^T : Q·Khi + Q·Klo ----
        float S[8][4];
#pragma unroll
        for (int i = 0; i < 8; i++)
#pragma unroll
            for (int j = 0; j < 4; j++) S[i][j] = 0.f;

        uint32_t bk[8][2];
#pragma unroll
        for (int kt = 0; kt < 4; kt++) {
            uint32_t colB = kt * 32 + bcolB;
#pragma unroll
            for (int g = 0; g < 4; g++)
                ldsm_x4(bk[2 * g][0], bk[2 * g][1], bk[2 * g + 1][0], bk[2 * g + 1][1],
                        KHIb + (g * 16 + brow) * APITCHB + colB);
#pragma unroll
            for (int nt = 0; nt < 8; nt++) mma16816(S[nt], aq[kt], bk[nt]);
#pragma unroll
            for (int g = 0; g < 4; g++)
                ldsm_x4(bk[2 * g][0], bk[2 * g][1], bk[2 * g + 1][0], bk[2 * g + 1][1],
                        KLOb + (g * 16 + brow) * APITCHB + colB);
#pragma unroll
            for (int nt = 0; nt < 8; nt++) mma16816(S[nt], aq[kt], bk[nt]);
        }

        // ---- online softmax (rows r0 = lane>>2, r1 = r0+8) ----
        float rm0 = -INFINITY, rm1 = -INFINITY;
#pragma unroll
        for (int j = 0; j < 8; j++) {
            rm0 = fmaxf(rm0, fmaxf(S[j][0], S[j][1]));
            rm1 = fmaxf(rm1, fmaxf(S[j][2], S[j][3]));
        }
        rm0 = fmaxf(rm0, __shfl_xor_sync(0xffffffffu, rm0, 1));
        rm0 = fmaxf(rm0, __shfl_xor_sync(0xffffffffu, rm0, 2));
        rm1 = fmaxf(rm1, __shfl_xor_sync(0xffffffffu, rm1, 1));
        rm1 = fmaxf(rm1, __shfl_xor_sync(0xffffffffu, rm1, 2));
        float mn0 = fmaxf(m0, rm0), mn1 = fmaxf(m1, rm1);
        float a0 = ex2f((m0 - mn0) * cc), a1 = ex2f((m1 - mn1) * cc);
        m0 = mn0; m1 = mn1;
        float mc0 = mn0 * cc, mc1 = mn1 * cc;

        uint32_t ph[4][4];
        float rs0 = 0.f, rs1 = 0.f;
#pragma unroll
        for (int j = 0; j < 8; j++) {
            float p0 = ex2f(fmaf(S[j][0], cc, -mc0));
            float p1 = ex2f(fmaf(S[j][1], cc, -mc0));
            float p2 = ex2f(fmaf(S[j][2], cc, -mc1));
            float p3 = ex2f(fmaf(S[j][3], cc, -mc1));
            rs0 += p0 + p1; rs1 += p2 + p3;
            int kt = j >> 1, hf = (j & 1) * 2;
            ph[kt][hf]     = packh(p0, p1);
            ph[kt][hf + 1] = packh(p2, p3);
        }
        rs0 += __shfl_xor_sync(0xffffffffu, rs0, 1);
        rs0 += __shfl_xor_sync(0xffffffffu, rs0, 2);
        rs1 += __shfl_xor_sync(0xffffffffu, rs1, 1);
        rs1 += __shfl_xor_sync(0xffffffffu, rs1, 2);
        l0 = l0 * a0 + rs0;
        l1 = l1 * a1 + rs1;
#pragma unroll
        for (int dt = 0; dt < 8; dt++) {
            O[dt][0] *= a0; O[dt][1] *= a0; O[dt][2] *= a1; O[dt][3] *= a1;
        }

        // ---- O += P V : P·Vhi + P·Vlo ----
        uint32_t bv[8][2];
#pragma unroll
        for (int kt = 0; kt < 4; kt++) {
            uint32_t rowB = (kt * 16 + vrow) * APITCHB + vcolB;
#pragma unroll
            for (int g2 = 0; g2 < 4; g2++)
                ldsm_x4_t(bv[2 * g2][0], bv[2 * g2][1], bv[2 * g2 + 1][0], bv[2 * g2 + 1][1],
                          VHIb + rowB + g2 * 32);
#pragma unroll
            for (int dt = 0; dt < 8; dt++) mma16816(O[dt], ph[kt], bv[dt]);
#pragma unroll
            for (int g2 = 0; g2 < 4; g2++)
                ldsm_x4_t(bv[2 * g2][0], bv[2 * g2][1], bv[2 * g2 + 1][0], bv[2 * g2 + 1][1],
                          VLOb + rowB + g2 * 32);
#pragma unroll
            for (int dt = 0; dt < 8; dt++) mma16816(O[dt], ph[kt], bv[dt]);
        }

        if (t + 2 < Nn / KVT)
            load_kv_tile(kvmats, KV0 + wstage * KVBUF, t + 2, tid);
        cp_commit();
        stage = (stage + 1) % 3; wstage = (wstage + 1) % 3;
    }

    // ---- epilogue: normalize, write fp16 hi/lo to g_Ahi/g_Alo [b*n][h*64+d] ----
    const int b = bh >> 4, h = bh & 15;
    float il0 = 1.f / l0, il1 = 1.f / l1;
    size_t row0 = (size_t)b * Nn + q0 + wid * 16 + (lane >> 2);
    size_t row1 = row0 + 8;
#pragma unroll
    for (int dt = 0; dt < 8; dt++) {
        int col = h * 64 + dt * 8 + (lane & 3) * 2;
        float v0 = O[dt][0] * il0, v1 = O[dt][1] * il0;
        float v2 = O[dt][2] * il1, v3 = O[dt][3] * il1;
        float h0 = __half2float(__float2half_rn(v0));
        float h1 = __half2float(__float2half_rn(v1));
        float h2 = __half2float(__float2half_rn(v2));
        float h3 = __half2float(__float2half_rn(v3));
        *(uint32_t*)(g_Ahi + row0 * Hh + col) = packh(h0, h1);
        *(uint32_t*)(g_Alo + row0 * Hh + col) = packh(v0 - h0, v1 - h1);
        *(uint32_t*)(g_Ahi + row1 * Hh + col) = packh(h2, h3);
        *(uint32_t*)(g_Alo + row1 * Hh + col) = packh(v2 - h2, v3 - h3);
    }
}

// ---------------------------------------------------------------------------
extern "C" void kernel_launch(void* const* d_in, const int* in_sizes, int n_in,
                              void* d_out, int out_size)
{
    const float* x    = (const float*)d_in[0];
    const float* x2   = (const float*)d_in[1];
    const float* Wqkv = (const float*)d_in[2];
    const float* Wout = (const float*)d_in[3];
    const float* bout = (const float*)d_in[4];
    float* out = (float*)d_out;

    // 0) fp32 -> fp16 splits / conversions
    {
        __half *xh, *xl, *x2h, *x2l, *wq, *wo;
        cudaGetSymbolAddress((void**)&xh,  g_Xhi);  cudaGetSymbolAddress((void**)&xl,  g_Xlo);
        cudaGetSymbolAddress((void**)&x2h, g_X2hi); cudaGetSymbolAddress((void**)&x2l, g_X2lo);
        cudaGetSymbolAddress((void**)&wq,  g_Wq);   cudaGetSymbolAddress((void**)&wo,  g_Wo);

        int n4 = M_TOT * Kdim / 4;
        split_kernel<<<(n4 + 255) / 256, 256>>>(x,  xh,  xl,  n4);
        split_kernel<<<(n4 + 255) / 256, 256>>>(x2, x2h, x2l, n4);
        tconv_kernel<<<dim3(3 * Hh / 32, Kdim / 32), dim3(32, 8)>>>(Wqkv, wq, 3 * Hh);
        tconv_kernel<<<dim3(Hh / 32,     Kdim / 32), dim3(32, 8)>>>(Wout, wo, Hh);
    }

    // 1) QKV projections (fp16 HMMA, 2-pass)
    cudaFuncSetAttribute(qkv_mma_kernel, cudaFuncAttributeMaxDynamicSharedMemorySize, GEMM_SMEM);
    qkv_mma_kernel<<<dim3(Hh / BNt, M_TOT / BMt, 3), 256, GEMM_SMEM>>>();

    // 2) Tensor-core flash attention (fp16, 2-pass S + 2-pass PV)
    cudaFuncSetAttribute(attn_mma_kernel, cudaFuncAttributeMaxDynamicSharedMemorySize, ATTN_SMEM);
    attn_mma_kernel<<<dim3(Nn / QT, Bb * NH), 256, ATTN_SMEM>>>();

    // 3) Output projection (fp16 HMMA, 2-pass)
    cudaFuncSetAttribute(proj_mma_kernel, cudaFuncAttributeMaxDynamicSharedMemorySize, GEMM_SMEM);
    proj_mma_kernel<<<dim3(Hh / BNt, M_TOT / BMt), 256, GEMM_SMEM>>>(bout, out);
}